// round 4
// baseline (speedup 1.0000x reference)
#include <cuda_runtime.h>

#define NN 100000
#define NE 1600000
#define CH 64

typedef unsigned long long ull;

// Scratch (device globals — no allocation allowed)
__device__ __align__(16) float g_q[NN*CH];
__device__ __align__(16) float g_k[NN*CH];
__device__ __align__(16) float g_v[NN*CH];
__device__ __align__(16) float g_skip[NN*CH];
__device__ __align__(16) float g_agg[NN*CH];
__device__ float g_den[NN];
__device__ double g_red[2];
__device__ int g_idx64;

__device__ __forceinline__ ull ffma2(ull a, ull b, ull c){
    ull d;
    asm("fma.rn.f32x2 %0, %1, %2, %3;" : "=l"(d) : "l"(a), "l"(b), "l"(c));
    return d;
}
__device__ __forceinline__ float hadd2(ull a){
    float x, y;
    asm("mov.b64 {%0, %1}, %2;" : "=f"(x), "=f"(y) : "l"(a));
    return x + y;
}

// ---------------------------------------------------------------------------
// detect dtype of edge_index (int64 vs int32), 1 warp
// ---------------------------------------------------------------------------
__global__ void k_detect(const unsigned int* __restrict__ ei32){
    unsigned int hi = ei32[2*threadIdx.x + 1];
    unsigned int b = __ballot_sync(0xffffffffu, hi != 0u);
    if (threadIdx.x == 0) g_idx64 = (b == 0u);
}

// ---------------------------------------------------------------------------
// zero accumulators (two kernels; also pads launch order so k_qkvs is 4th)
// ---------------------------------------------------------------------------
__global__ void k_zero_agg(){
    int i = blockIdx.x*blockDim.x + threadIdx.x;          // NN*16 float4
    reinterpret_cast<float4*>(g_agg)[i] = make_float4(0.f,0.f,0.f,0.f);
}
__global__ void k_zero_den(){
    int i = blockIdx.x*blockDim.x + threadIdx.x;
    if (i < NN/4)
        reinterpret_cast<float4*>(g_den)[i] = make_float4(0.f,0.f,0.f,0.f);
    if (i == 0){ g_red[0] = 0.0; g_red[1] = 0.0; }
}

// ---------------------------------------------------------------------------
// qkvs v3: thread = node. W (64KB) + biases in smem, broadcast-read per
// channel (all lanes of a warp share (m, c) and stream 32 nodes). x row held
// in 64 registers, read once per (node, matrix) from a padded smem tile
// (68-float row stride -> conflict-free LDS.128).
// warp w: matrix m = w&3, node-half = w>>2. Tile = 64 nodes/block-iter.
// grid = 521, 3 tiles each (1563 tiles total, last partial, predicated).
// ---------------------------------------------------------------------------
#define QKV_SMEM_FLOATS (4*64*64 + 2*64*68 + 256)
#define QKV_SMEM_BYTES  (QKV_SMEM_FLOATS*4)

__global__ void __launch_bounds__(256, 2) k_qkvs(
    const float* __restrict__ geo, const float* __restrict__ euc,
    const float* __restrict__ Wq, const float* __restrict__ bq,
    const float* __restrict__ Wk, const float* __restrict__ bk,
    const float* __restrict__ Wv, const float* __restrict__ bv,
    const float* __restrict__ Ws, const float* __restrict__ bs)
{
    extern __shared__ float sm[];
    float* w_s = sm;                       // [4][64][64]
    float* x_s = sm + 4*64*64;             // [2][64][68]  (0=euc, 1=geo)
    float* b_s = x_s + 2*64*68;            // [256]

    const int tid = threadIdx.x;

    // stage W: 4096 float4, 16 per thread; m uniform within each j-step
    {
        const float4* Wsrc[4] = {(const float4*)Wq, (const float4*)Wk,
                                 (const float4*)Wv, (const float4*)Ws};
        float4* wd = reinterpret_cast<float4*>(w_s);
        #pragma unroll
        for (int j = 0; j < 16; j++){
            int idx = j*256 + tid;          // 0..4095
            wd[idx] = Wsrc[idx >> 10][idx & 1023];
        }
        b_s[tid] = (tid < 64) ? bq[tid] :
                   (tid < 128) ? bk[tid-64] :
                   (tid < 192) ? bv[tid-128] : bs[tid-192];
    }

    const int wid  = tid >> 5;
    const int lane = tid & 31;
    const int m    = wid & 3;
    const int nl   = (wid >> 2)*32 + lane;      // node-local 0..63
    const int s    = (m == 0 || m == 3) ? 0 : 1;
    float* OUT = (m==0)?g_q:(m==1)?g_k:(m==2)?g_v:g_skip;

    __syncthreads();

    #pragma unroll 1
    for (int k = 0; k < 3; k++){
        const int t = blockIdx.x + k*521;        // tile id 0..1562
        const int base = t*64;

        // stage x tile: 2048 float4 (euc+geo, 64 nodes), 8 per thread
        #pragma unroll
        for (int j = 0; j < 8; j++){
            int f = j*256 + tid;                 // 0..2047
            int src = f >> 10;                   // 0 euc, 1 geo
            int r = f & 1023;
            int nloc = r >> 4;
            int chunk = r & 15;
            int node = base + nloc;
            if (node < NN){
                const float* X = src ? geo : euc;
                float4 v = *reinterpret_cast<const float4*>(X + (size_t)node*CH + chunk*4);
                *reinterpret_cast<float4*>(x_s + (src*64 + nloc)*68 + chunk*4) = v;
            }
        }
        __syncthreads();

        const int node = base + nl;
        // x row -> 32 f32x2 registers
        ull x[32];
        {
            const ulonglong2* xr =
                reinterpret_cast<const ulonglong2*>(x_s + (s*64 + nl)*68);
            #pragma unroll
            for (int j = 0; j < 16; j++){
                ulonglong2 v = xr[j];
                x[2*j] = v.x; x[2*j+1] = v.y;
            }
        }
        float* ob = OUT + (size_t)node*CH;
        const bool ok = (node < NN);
        float4 buf;
        #pragma unroll 4
        for (int c = 0; c < 64; c++){
            const ulonglong2* wp =
                reinterpret_cast<const ulonglong2*>(w_s + ((m << 6) + c)*64);
            ull a0 = 0ull, a1 = 0ull;
            #pragma unroll
            for (int j = 0; j < 16; j++){
                ulonglong2 wv = wp[j];
                a0 = ffma2(x[2*j],   wv.x, a0);
                a1 = ffma2(x[2*j+1], wv.y, a1);
            }
            float r = hadd2(a0) + hadd2(a1) + b_s[(m << 6) + c];
            (&buf.x)[c & 3] = r;
            if ((c & 3) == 3 && ok)
                *reinterpret_cast<float4*>(ob + (c - 3)) = buf;
        }
        __syncthreads();   // protect x_s before next tile's stores
    }
}

// ---------------------------------------------------------------------------
// fused edge pass, 4 lanes/edge (unchanged from R3 — profiled next round)
// ---------------------------------------------------------------------------
__global__ void k_edge(const void* __restrict__ ei_raw){
    const int gt  = blockIdx.x*blockDim.x + threadIdx.x;
    const int e   = gt >> 2;
    const int sub = threadIdx.x & 3;

    int src, dst;
    if (g_idx64){
        const long long* ei = (const long long*)ei_raw;
        src = (int)__ldg(ei + e);
        dst = (int)__ldg(ei + NE + e);
    } else {
        const int* ei = (const int*)ei_raw;
        src = __ldg(ei + e);
        dst = __ldg(ei + NE + e);
    }
    src = min(max(src, 0), NN-1);
    dst = min(max(dst, 0), NN-1);

    const float4* qp = reinterpret_cast<const float4*>(g_q) + (size_t)dst*16;
    const float4* kp = reinterpret_cast<const float4*>(g_k) + (size_t)src*16;
    const float4* vp = reinterpret_cast<const float4*>(g_v) + (size_t)src*16;

    float4 q0 = qp[sub],   q1 = qp[sub+4],  q2 = qp[sub+8],  q3 = qp[sub+12];
    float4 k0 = kp[sub],   k1 = kp[sub+4],  k2 = kp[sub+8],  k3 = kp[sub+12];
    float4 v0 = vp[sub],   v1 = vp[sub+4],  v2 = vp[sub+8],  v3 = vp[sub+12];

    float d = q0.x*k0.x + q0.y*k0.y + q0.z*k0.z + q0.w*k0.w
            + q1.x*k1.x + q1.y*k1.y + q1.z*k1.z + q1.w*k1.w
            + q2.x*k2.x + q2.y*k2.y + q2.z*k2.z + q2.w*k2.w
            + q3.x*k3.x + q3.y*k3.y + q3.z*k3.z + q3.w*k3.w;
    d += __shfl_xor_sync(0xffffffffu, d, 2);
    d += __shfl_xor_sync(0xffffffffu, d, 1);
    const float ex = __expf(d * 0.125f);   // 1/sqrt(64)

    if (sub == 0) atomicAdd(g_den + dst, ex);

    float* ap = g_agg + (size_t)dst*CH;
    asm volatile("red.global.add.v4.f32 [%0], {%1, %2, %3, %4};"
        :: "l"(ap + sub*4),      "f"(ex*v0.x), "f"(ex*v0.y), "f"(ex*v0.z), "f"(ex*v0.w) : "memory");
    asm volatile("red.global.add.v4.f32 [%0], {%1, %2, %3, %4};"
        :: "l"(ap + 16 + sub*4), "f"(ex*v1.x), "f"(ex*v1.y), "f"(ex*v1.z), "f"(ex*v1.w) : "memory");
    asm volatile("red.global.add.v4.f32 [%0], {%1, %2, %3, %4};"
        :: "l"(ap + 32 + sub*4), "f"(ex*v2.x), "f"(ex*v2.y), "f"(ex*v2.z), "f"(ex*v2.w) : "memory");
    asm volatile("red.global.add.v4.f32 [%0], {%1, %2, %3, %4};"
        :: "l"(ap + 48 + sub*4), "f"(ex*v3.x), "f"(ex*v3.y), "f"(ex*v3.z), "f"(ex*v3.w) : "memory");
}

// ---------------------------------------------------------------------------
// out_pre = agg/(den+1e-16) + skip ; global sum/sumsq
// ---------------------------------------------------------------------------
__global__ void k_final1(float* __restrict__ out){
    float lsum = 0.f, lsq = 0.f;
    const float4* agg4  = reinterpret_cast<const float4*>(g_agg);
    const float4* skip4 = reinterpret_cast<const float4*>(g_skip);
    float4* out4 = reinterpret_cast<float4*>(out);
    for (int i = blockIdx.x*blockDim.x + threadIdx.x; i < NN*16;
         i += gridDim.x*blockDim.x){
        float4 a = agg4[i];
        float4 s = skip4[i];
        const float inv = 1.f / (g_den[i>>4] + 1e-16f);
        float4 val;
        val.x = a.x*inv + s.x;  val.y = a.y*inv + s.y;
        val.z = a.z*inv + s.z;  val.w = a.w*inv + s.w;
        out4[i] = val;
        lsum += val.x + val.y + val.z + val.w;
        lsq  += val.x*val.x + val.y*val.y + val.z*val.z + val.w*val.w;
    }
    #pragma unroll
    for (int off=16; off>0; off>>=1){
        lsum += __shfl_xor_sync(0xffffffffu, lsum, off);
        lsq  += __shfl_xor_sync(0xffffffffu, lsq,  off);
    }
    __shared__ float s1[8], s2[8];
    const int wid = threadIdx.x >> 5;
    if ((threadIdx.x & 31) == 0){ s1[wid] = lsum; s2[wid] = lsq; }
    __syncthreads();
    if (threadIdx.x == 0){
        float ts = 0.f, tq = 0.f;
        #pragma unroll
        for (int i=0;i<8;i++){ ts += s1[i]; tq += s2[i]; }
        atomicAdd(&g_red[0], (double)ts);
        atomicAdd(&g_red[1], (double)tq);
    }
}

// ---------------------------------------------------------------------------
// graph layernorm + relu
// ---------------------------------------------------------------------------
__global__ void k_final2(float* __restrict__ out,
                         const float* __restrict__ lnw,
                         const float* __restrict__ lnb){
    const int i = blockIdx.x*blockDim.x + threadIdx.x;
    if (i >= NN*16) return;
    const double invM = 1.0 / (double)(NN*CH);
    const float mean = (float)(g_red[0]*invM);
    const float var  = (float)(g_red[1]*invM) - mean*mean;
    const float rstd = 1.f / (sqrtf(fmaxf(var, 0.f)) + 1e-5f);
    const int cb = (i & 15) * 4;
    const float4 wv = *reinterpret_cast<const float4*>(lnw + cb);
    const float4 bv = *reinterpret_cast<const float4*>(lnb + cb);
    float4 x = reinterpret_cast<float4*>(out)[i];
    float4 y;
    y.x = fmaxf((x.x - mean)*rstd*wv.x + bv.x, 0.f);
    y.y = fmaxf((x.y - mean)*rstd*wv.y + bv.y, 0.f);
    y.z = fmaxf((x.z - mean)*rstd*wv.z + bv.z, 0.f);
    y.w = fmaxf((x.w - mean)*rstd*wv.w + bv.w, 0.f);
    reinterpret_cast<float4*>(out)[i] = y;
}

// ---------------------------------------------------------------------------
extern "C" void kernel_launch(void* const* d_in, const int* in_sizes, int n_in,
                              void* d_out, int out_size){
    const float* geo = (const float*)d_in[0];
    const float* euc = (const float*)d_in[1];
    const float* Wq  = (const float*)d_in[2];
    const float* bq  = (const float*)d_in[3];
    const float* Wk  = (const float*)d_in[4];
    const float* bk  = (const float*)d_in[5];
    const float* Wv  = (const float*)d_in[6];
    const float* bv  = (const float*)d_in[7];
    const float* Ws  = (const float*)d_in[8];
    const float* bs  = (const float*)d_in[9];
    const float* lnw = (const float*)d_in[10];
    const float* lnb = (const float*)d_in[11];

    const void* ei = d_in[12];
    for (int i = 0; i < n_in; i++)
        if (in_sizes[i] == 2*NE){ ei = d_in[i]; break; }

    float* out = (float*)d_out;

    cudaFuncSetAttribute(k_qkvs, cudaFuncAttributeMaxDynamicSharedMemorySize,
                         QKV_SMEM_BYTES);

    k_detect  <<<1, 32>>>((const unsigned int*)ei);
    k_zero_agg<<<NN*16/256, 256>>>();
    k_zero_den<<<(NN/4 + 255)/256, 256>>>();
    k_qkvs    <<<521, 256, QKV_SMEM_BYTES>>>(geo, euc, Wq, bq, Wk, bk, Wv, bv, Ws, bs);
    k_edge    <<<NE*4/256, 256>>>(ei);
    k_final1  <<<592, 256>>>(out);
    k_final2  <<<(NN*16 + 255)/256, 256>>>(out, lnw, lnb);
}